// round 1
// baseline (speedup 1.0000x reference)
#include <cuda_runtime.h>
#include <cuda_bf16.h>
#include <cstdint>

#define NN 50000
#define HH 128
#define OUTC 64
#define DEPTH 3
#define LN_EPS 1e-5f

// ---------------- scratch (static __device__ arrays; no allocations) ----------------
__device__ float g_x[NN * HH];
__device__ float g_hG[NN * HH];
__device__ float g_hL[NN * HH];
__device__ float g_aggG[NN * HH];
__device__ float g_aggL[NN * HH];
__device__ float g_xcat[NN * 2 * HH];
__device__ int   g_degG[NN];
__device__ int   g_degL[NN];
__device__ float g_dinvG[NN];
__device__ float g_dinvL[NN];

// ---------------- small kernels ----------------
__global__ void zero_deg_kernel(int* degG, int* degL, int n) {
    int i = blockIdx.x * blockDim.x + threadIdx.x;
    if (i < n) { degG[i] = 0; degL[i] = 0; }
}

__global__ void count_deg_kernel(const int* __restrict__ dst, int E, int* __restrict__ deg) {
    int i = blockIdx.x * blockDim.x + threadIdx.x;
    if (i < E) atomicAdd(&deg[dst[i]], 1);
}

__global__ void make_dinv_kernel(const int* __restrict__ degG, float* __restrict__ dinvG,
                                 const int* __restrict__ degL, float* __restrict__ dinvL, int n) {
    int i = blockIdx.x * blockDim.x + threadIdx.x;
    if (i < n) {
        dinvG[i] = rsqrtf((float)degG[i] + 2.0f);
        dinvL[i] = rsqrtf((float)degL[i] + 2.0f);
    }
}

// agg = h * (2*dinv^2) + bias   (self-loop contribution + bias), for both branches
__global__ void agg_init_kernel(const float* __restrict__ hG, const float* __restrict__ hL,
                                const float* __restrict__ dinvG, const float* __restrict__ dinvL,
                                const float* __restrict__ bG, const float* __restrict__ bL,
                                float* __restrict__ aggG, float* __restrict__ aggL) {
    int idx = blockIdx.x * blockDim.x + threadIdx.x;
    if (idx >= NN * HH) return;
    int n = idx >> 7;
    int j = idx & 127;
    float dg = dinvG[n];
    float dl = dinvL[n];
    aggG[idx] = hG[idx] * (2.0f * dg * dg) + bG[j];
    aggL[idx] = hL[idx] * (2.0f * dl * dl) + bL[j];
}

// warp-per-edge scatter:  agg[dst] += h[src] * dinv[src]*dinv[dst]   (vector red.v4)
__global__ void scatter_kernel(const float4* __restrict__ h4, const float* __restrict__ dinv,
                               float4* __restrict__ agg4,
                               const int* __restrict__ src, const int* __restrict__ dst, int E) {
    int gt = blockIdx.x * blockDim.x + threadIdx.x;
    int w = gt >> 5;
    int lane = threadIdx.x & 31;
    if (w >= E) return;
    int s = __ldg(&src[w]);
    int d = __ldg(&dst[w]);
    float coef = __ldg(&dinv[s]) * __ldg(&dinv[d]);
    float4 v = h4[s * (HH / 4) + lane];
    v.x *= coef; v.y *= coef; v.z *= coef; v.w *= coef;
    float4* p = &agg4[d * (HH / 4) + lane];
    asm volatile("red.global.add.v4.f32 [%0], {%1, %2, %3, %4};"
                 :: "l"(p), "f"(v.x), "f"(v.y), "f"(v.z), "f"(v.w) : "memory");
}

// LayerNorm + ReLU + optional residual, writes concat [xG | xL] rows of width 256
__global__ void ln_post_kernel(const float* __restrict__ aggG, const float* __restrict__ aggL,
                               const float* __restrict__ x,
                               const float* __restrict__ gamma, const float* __restrict__ beta,
                               float* __restrict__ xcat, int residual) {
    int n = blockIdx.x;
    int t = threadIdx.x;
    __shared__ float red[8];
    const float* srcs[2] = { aggG, aggL };
    #pragma unroll
    for (int br = 0; br < 2; br++) {
        float v = srcs[br][n * HH + t];
        float s1 = v, s2 = v * v;
        #pragma unroll
        for (int o = 16; o > 0; o >>= 1) {
            s1 += __shfl_xor_sync(0xffffffffu, s1, o);
            s2 += __shfl_xor_sync(0xffffffffu, s2, o);
        }
        if ((t & 31) == 0) { red[t >> 5] = s1; red[4 + (t >> 5)] = s2; }
        __syncthreads();
        float S1 = red[0] + red[1] + red[2] + red[3];
        float S2 = red[4] + red[5] + red[6] + red[7];
        float mu = S1 * (1.0f / HH);
        float var = S2 * (1.0f / HH) - mu * mu;
        float y = (v - mu) * rsqrtf(var + LN_EPS) * gamma[t] + beta[t];
        y = fmaxf(y, 0.0f);
        if (residual) y += x[n * HH + t];
        xcat[n * (2 * HH) + br * HH + t] = y;   // br=0 -> xG cols 0..127, br=1 -> xL cols 128..255
        __syncthreads();
    }
}

// ---------------- SGEMM: C[M,Nc] = A[M,K] @ B[K,Nc] (+bias) ----------------
// BM=64, BN=64, BK=32, 256 threads, 4x4 per thread
__global__ void sgemm_bias_kernel(const float* __restrict__ A, const float* __restrict__ B,
                                  const float* __restrict__ bias, float* __restrict__ C,
                                  int M, int Nc, int K) {
    __shared__ float As[64][32];
    __shared__ float Bs[32][64];
    int tid = threadIdx.x;
    int tx = tid & 15;        // 0..15 (col group)
    int ty = tid >> 4;        // 0..15 (row group)
    int row0 = blockIdx.y * 64;
    int col0 = blockIdx.x * 64;

    float acc[4][4];
    #pragma unroll
    for (int i = 0; i < 4; i++)
        #pragma unroll
        for (int j = 0; j < 4; j++) acc[i][j] = 0.0f;

    for (int kk = 0; kk < K; kk += 32) {
        // load A tile: 64x32 floats = 512 float4, 2 per thread
        #pragma unroll
        for (int i = 0; i < 2; i++) {
            int f = tid + i * 256;          // 0..511
            int r = f >> 3;                 // row 0..63
            int c4 = f & 7;                 // float4 col 0..7
            int grow = row0 + r;
            float4 av = make_float4(0.f, 0.f, 0.f, 0.f);
            if (grow < M)
                av = *reinterpret_cast<const float4*>(&A[(size_t)grow * K + kk + c4 * 4]);
            *reinterpret_cast<float4*>(&As[r][c4 * 4]) = av;
        }
        // load B tile: 32x64 floats = 512 float4, 2 per thread
        #pragma unroll
        for (int i = 0; i < 2; i++) {
            int f = tid + i * 256;
            int r = f >> 4;                 // row 0..31
            int c4 = f & 15;                // float4 col 0..15
            float4 bv = *reinterpret_cast<const float4*>(&B[(size_t)(kk + r) * Nc + col0 + c4 * 4]);
            *reinterpret_cast<float4*>(&Bs[r][c4 * 4]) = bv;
        }
        __syncthreads();

        #pragma unroll
        for (int k = 0; k < 32; k++) {
            float4 bv = *reinterpret_cast<const float4*>(&Bs[k][tx * 4]);
            float a0 = As[ty * 4 + 0][k];
            float a1 = As[ty * 4 + 1][k];
            float a2 = As[ty * 4 + 2][k];
            float a3 = As[ty * 4 + 3][k];
            acc[0][0] += a0 * bv.x; acc[0][1] += a0 * bv.y; acc[0][2] += a0 * bv.z; acc[0][3] += a0 * bv.w;
            acc[1][0] += a1 * bv.x; acc[1][1] += a1 * bv.y; acc[1][2] += a1 * bv.z; acc[1][3] += a1 * bv.w;
            acc[2][0] += a2 * bv.x; acc[2][1] += a2 * bv.y; acc[2][2] += a2 * bv.z; acc[2][3] += a2 * bv.w;
            acc[3][0] += a3 * bv.x; acc[3][1] += a3 * bv.y; acc[3][2] += a3 * bv.z; acc[3][3] += a3 * bv.w;
        }
        __syncthreads();
    }

    float4 bv4 = make_float4(0.f, 0.f, 0.f, 0.f);
    if (bias) bv4 = *reinterpret_cast<const float4*>(&bias[col0 + tx * 4]);
    #pragma unroll
    for (int i = 0; i < 4; i++) {
        int r = row0 + ty * 4 + i;
        if (r < M) {
            float4 o;
            o.x = acc[i][0] + bv4.x;
            o.y = acc[i][1] + bv4.y;
            o.z = acc[i][2] + bv4.z;
            o.w = acc[i][3] + bv4.w;
            *reinterpret_cast<float4*>(&C[(size_t)r * Nc + col0 + tx * 4]) = o;
        }
    }
}

// ---------------- launch ----------------
extern "C" void kernel_launch(void* const* d_in, const int* in_sizes, int n_in,
                              void* d_out, int out_size) {
    const float* x_in  = (const float*)d_in[0];
    const float* WL    = (const float*)d_in[1];
    const float* bL    = (const float*)d_in[2];
    const float* WG    = (const float*)d_in[3];
    const float* bG    = (const float*)d_in[4];
    const float* linW  = (const float*)d_in[5];
    const float* linb  = (const float*)d_in[6];
    const float* ln_g  = (const float*)d_in[7];
    const float* ln_b  = (const float*)d_in[8];
    const float* finW  = (const float*)d_in[9];
    const float* finb  = (const float*)d_in[10];
    const int*   Ge    = (const int*)d_in[11];
    const int*   Le    = (const int*)d_in[12];
    int E_G = in_sizes[11] / 2;
    int E_L = in_sizes[12] / 2;
    float* out = (float*)d_out;

    float *px, *phG, *phL, *paggG, *paggL, *pxcat, *pdinvG, *pdinvL;
    int *pdegG, *pdegL;
    cudaGetSymbolAddress((void**)&px,     g_x);
    cudaGetSymbolAddress((void**)&phG,    g_hG);
    cudaGetSymbolAddress((void**)&phL,    g_hL);
    cudaGetSymbolAddress((void**)&paggG,  g_aggG);
    cudaGetSymbolAddress((void**)&paggL,  g_aggL);
    cudaGetSymbolAddress((void**)&pxcat,  g_xcat);
    cudaGetSymbolAddress((void**)&pdegG,  g_degG);
    cudaGetSymbolAddress((void**)&pdegL,  g_degL);
    cudaGetSymbolAddress((void**)&pdinvG, g_dinvG);
    cudaGetSymbolAddress((void**)&pdinvL, g_dinvL);

    cudaMemcpyAsync(px, x_in, (size_t)NN * HH * sizeof(float), cudaMemcpyDeviceToDevice);

    // degrees / dinv (fixed per call, recomputed deterministically)
    zero_deg_kernel<<<(NN + 255) / 256, 256>>>(pdegG, pdegL, NN);
    count_deg_kernel<<<(E_G + 255) / 256, 256>>>(Ge + E_G, E_G, pdegG);
    count_deg_kernel<<<(E_L + 255) / 256, 256>>>(Le + E_L, E_L, pdegL);
    make_dinv_kernel<<<(NN + 255) / 256, 256>>>(pdegG, pdinvG, pdegL, pdinvL, NN);

    dim3 gH(HH / 64, (NN + 63) / 64);

    for (int i = 0; i < DEPTH; i++) {
        // h = x @ W  (both branches)
        sgemm_bias_kernel<<<gH, 256>>>(px, WG + (size_t)i * HH * HH, nullptr, phG, NN, HH, HH);
        sgemm_bias_kernel<<<gH, 256>>>(px, WL + (size_t)i * HH * HH, nullptr, phL, NN, HH, HH);
        // self-loop + bias init
        agg_init_kernel<<<(NN * HH + 255) / 256, 256>>>(phG, phL, pdinvG, pdinvL,
                                                        bG + (size_t)i * HH, bL + (size_t)i * HH,
                                                        paggG, paggL);
        // edge scatter
        scatter_kernel<<<((size_t)E_G * 32 + 255) / 256, 256>>>((const float4*)phG, pdinvG,
                                                                (float4*)paggG, Ge, Ge + E_G, E_G);
        scatter_kernel<<<((size_t)E_L * 32 + 255) / 256, 256>>>((const float4*)phL, pdinvL,
                                                                (float4*)paggL, Le, Le + E_L, E_L);
        // LN + relu + residual + concat
        ln_post_kernel<<<NN, 128>>>(paggG, paggL, px, ln_g, ln_b, pxcat, (i > 0) ? 1 : 0);
        // x = xcat @ linW + linb
        sgemm_bias_kernel<<<gH, 256>>>(pxcat, linW + (size_t)i * 2 * HH * HH,
                                       linb + (size_t)i * HH, px, NN, HH, 2 * HH);
    }

    // out1 = x @ finW + finb
    dim3 gF(OUTC / 64, (NN + 63) / 64);
    sgemm_bias_kernel<<<gF, 256>>>(px, finW, finb, out, NN, OUTC, HH);
    // out2 = x
    cudaMemcpyAsync(out + (size_t)NN * OUTC, px, (size_t)NN * HH * sizeof(float),
                    cudaMemcpyDeviceToDevice);
}

// round 2
// speedup vs baseline: 1.3535x; 1.3535x over previous
#include <cuda_runtime.h>
#include <cuda_bf16.h>
#include <cstdint>

#define NN 50000
#define HH 128
#define OUTC 64
#define DEPTH 3
#define LN_EPS 1e-5f
#define EGMAX 600000
#define ELMAX 400000
#define NB196 196   // ceil(NN/256)

// ---------------- scratch ----------------
__device__ float g_x[NN * HH];
__device__ float g_hG[NN * HH];
__device__ float g_hL[NN * HH];
__device__ float g_xcat[NN * 2 * HH];
__device__ int   g_degG[NN];
__device__ int   g_degL[NN];
__device__ float g_dinvG[NN];
__device__ float g_dinvL[NN];
__device__ int   g_rowptrG[NN + 1];
__device__ int   g_rowptrL[NN + 1];
__device__ int   g_fillG[NN];
__device__ int   g_fillL[NN];
__device__ int   g_colG[EGMAX];
__device__ int   g_colL[ELMAX];
__device__ float g_coefG[EGMAX];
__device__ float g_coefL[ELMAX];
__device__ int   g_bsum[256];

// ---------------- degree / dinv ----------------
__global__ void zero_deg_kernel(int* degG, int* degL, int n) {
    int i = blockIdx.x * blockDim.x + threadIdx.x;
    if (i < n) { degG[i] = 0; degL[i] = 0; }
}

__global__ void count_deg_kernel(const int* __restrict__ dst, int E, int* __restrict__ deg) {
    int i = blockIdx.x * blockDim.x + threadIdx.x;
    if (i < E) atomicAdd(&deg[dst[i]], 1);
}

__global__ void make_dinv_kernel(const int* __restrict__ degG, float* __restrict__ dinvG,
                                 const int* __restrict__ degL, float* __restrict__ dinvL, int n) {
    int i = blockIdx.x * blockDim.x + threadIdx.x;
    if (i < n) {
        dinvG[i] = rsqrtf((float)degG[i] + 2.0f);
        dinvL[i] = rsqrtf((float)degL[i] + 2.0f);
    }
}

// ---------------- CSR build ----------------
__global__ void scan_block_kernel(const int* __restrict__ deg, int* __restrict__ rowptr,
                                  int* __restrict__ bsum, int n) {
    __shared__ int s[256];
    int i = blockIdx.x * 256 + threadIdx.x;
    int v = (i < n) ? deg[i] : 0;
    s[threadIdx.x] = v;
    __syncthreads();
    #pragma unroll
    for (int o = 1; o < 256; o <<= 1) {
        int t = (threadIdx.x >= o) ? s[threadIdx.x - o] : 0;
        __syncthreads();
        s[threadIdx.x] += t;
        __syncthreads();
    }
    if (i < n) rowptr[i] = s[threadIdx.x] - v;   // exclusive
    if (threadIdx.x == 255) bsum[blockIdx.x] = s[255];
}

__global__ void scan_aux_kernel(int* bsum, int nb) {
    if (threadIdx.x == 0 && blockIdx.x == 0) {
        int run = 0;
        for (int i = 0; i < nb; i++) { int t = bsum[i]; bsum[i] = run; run += t; }
    }
}

__global__ void scan_add_kernel(int* __restrict__ rowptr, int* __restrict__ fill,
                                const int* __restrict__ bsum, int n, int E) {
    int i = blockIdx.x * 256 + threadIdx.x;
    if (i < n) {
        int v = rowptr[i] + bsum[i >> 8];
        rowptr[i] = v;
        fill[i] = v;
    }
    if (i == 0) rowptr[n] = E;
}

__global__ void fill_csr_kernel(const int* __restrict__ src, const int* __restrict__ dst, int E,
                                int* __restrict__ fill, int* __restrict__ col,
                                float* __restrict__ coef, const float* __restrict__ dinv) {
    int e = blockIdx.x * blockDim.x + threadIdx.x;
    if (e < E) {
        int s = src[e], d = dst[e];
        int p = atomicAdd(&fill[d], 1);
        col[p] = s;
        coef[p] = dinv[s] * dinv[d];
    }
}

// ---------------- fused gather + self-loop + bias + LN + ReLU + residual + concat ----------------
// one warp per node; lane owns 4 channels (float4). half=0 -> cols 0..127, half=1 -> 128..255
__global__ void gather_ln_kernel(const float4* __restrict__ h4, const float4* __restrict__ x4,
                                 const int* __restrict__ rowptr, const int* __restrict__ col,
                                 const float* __restrict__ coef, const float* __restrict__ dinv,
                                 const float4* __restrict__ bias4, const float4* __restrict__ g4,
                                 const float4* __restrict__ b4, float4* __restrict__ xcat4,
                                 int half, int residual) {
    int warp = (blockIdx.x * blockDim.x + threadIdx.x) >> 5;
    int lane = threadIdx.x & 31;
    if (warp >= NN) return;
    int n = warp;

    float dv = __ldg(&dinv[n]);
    float sl = 2.0f * dv * dv;
    float4 h = h4[n * 32 + lane];
    float4 bb = __ldg(&bias4[lane]);
    float4 acc;
    acc.x = h.x * sl + bb.x;
    acc.y = h.y * sl + bb.y;
    acc.z = h.z * sl + bb.z;
    acc.w = h.w * sl + bb.w;

    int e0 = __ldg(&rowptr[n]);
    int e1 = __ldg(&rowptr[n + 1]);
    for (int e = e0; e < e1; e++) {
        int s = __ldg(&col[e]);
        float c = __ldg(&coef[e]);
        float4 v = h4[s * 32 + lane];
        acc.x += c * v.x;
        acc.y += c * v.y;
        acc.z += c * v.z;
        acc.w += c * v.w;
    }

    // LayerNorm across 128 channels (warp reduce)
    float s1 = acc.x + acc.y + acc.z + acc.w;
    float s2 = acc.x * acc.x + acc.y * acc.y + acc.z * acc.z + acc.w * acc.w;
    #pragma unroll
    for (int o = 16; o > 0; o >>= 1) {
        s1 += __shfl_xor_sync(0xffffffffu, s1, o);
        s2 += __shfl_xor_sync(0xffffffffu, s2, o);
    }
    float mu = s1 * (1.0f / HH);
    float var = s2 * (1.0f / HH) - mu * mu;
    float rstd = rsqrtf(var + LN_EPS);

    float4 gg = __ldg(&g4[lane]);
    float4 be = __ldg(&b4[lane]);
    float4 y;
    y.x = fmaxf((acc.x - mu) * rstd * gg.x + be.x, 0.0f);
    y.y = fmaxf((acc.y - mu) * rstd * gg.y + be.y, 0.0f);
    y.z = fmaxf((acc.z - mu) * rstd * gg.z + be.z, 0.0f);
    y.w = fmaxf((acc.w - mu) * rstd * gg.w + be.w, 0.0f);
    if (residual) {
        float4 xv = x4[n * 32 + lane];
        y.x += xv.x; y.y += xv.y; y.z += xv.z; y.w += xv.w;
    }
    xcat4[n * 64 + half * 32 + lane] = y;
}

// ---------------- SGEMM 128x128x16, 256 threads, 8x8 per thread ----------------
__global__ void sgemm128_kernel(const float* __restrict__ A, const float* __restrict__ B,
                                const float* __restrict__ bias, float* __restrict__ C,
                                int M, int Nc, int K) {
    __shared__ float As[16][128];
    __shared__ float Bs[16][128];
    int tid = threadIdx.x;
    int row0 = blockIdx.y * 128;
    int col0 = blockIdx.x * 128;
    int rm = (tid >> 4) * 8;
    int rn = (tid & 15) * 8;

    float acc[8][8];
    #pragma unroll
    for (int i = 0; i < 8; i++)
        #pragma unroll
        for (int j = 0; j < 8; j++) acc[i][j] = 0.0f;

    for (int kk = 0; kk < K; kk += 16) {
        // A tile 128x16 -> transposed into As[k][m]
        #pragma unroll
        for (int it = 0; it < 2; it++) {
            int f = tid + it * 256;       // 0..511
            int r = f >> 2;               // 0..127
            int c4 = f & 3;               // 0..3
            int grow = row0 + r;
            float4 av = make_float4(0.f, 0.f, 0.f, 0.f);
            if (grow < M)
                av = *reinterpret_cast<const float4*>(&A[(size_t)grow * K + kk + c4 * 4]);
            As[c4 * 4 + 0][r] = av.x;
            As[c4 * 4 + 1][r] = av.y;
            As[c4 * 4 + 2][r] = av.z;
            As[c4 * 4 + 3][r] = av.w;
        }
        // B tile 16x128
        #pragma unroll
        for (int it = 0; it < 2; it++) {
            int f = tid + it * 256;
            int r = f >> 5;               // 0..15
            int c4 = f & 31;              // 0..31
            float4 bv = *reinterpret_cast<const float4*>(&B[(size_t)(kk + r) * Nc + col0 + c4 * 4]);
            *reinterpret_cast<float4*>(&Bs[r][c4 * 4]) = bv;
        }
        __syncthreads();

        #pragma unroll
        for (int k = 0; k < 16; k++) {
            float4 a0 = *reinterpret_cast<const float4*>(&As[k][rm]);
            float4 a1 = *reinterpret_cast<const float4*>(&As[k][rm + 4]);
            float4 b0 = *reinterpret_cast<const float4*>(&Bs[k][rn]);
            float4 b1 = *reinterpret_cast<const float4*>(&Bs[k][rn + 4]);
            float ar[8] = {a0.x, a0.y, a0.z, a0.w, a1.x, a1.y, a1.z, a1.w};
            float br[8] = {b0.x, b0.y, b0.z, b0.w, b1.x, b1.y, b1.z, b1.w};
            #pragma unroll
            for (int i = 0; i < 8; i++)
                #pragma unroll
                for (int j = 0; j < 8; j++)
                    acc[i][j] += ar[i] * br[j];
        }
        __syncthreads();
    }

    float4 bv0 = make_float4(0.f, 0.f, 0.f, 0.f);
    float4 bv1 = bv0;
    if (bias) {
        bv0 = *reinterpret_cast<const float4*>(&bias[col0 + rn]);
        bv1 = *reinterpret_cast<const float4*>(&bias[col0 + rn + 4]);
    }
    #pragma unroll
    for (int i = 0; i < 8; i++) {
        int r = row0 + rm + i;
        if (r < M) {
            float4 o0, o1;
            o0.x = acc[i][0] + bv0.x; o0.y = acc[i][1] + bv0.y;
            o0.z = acc[i][2] + bv0.z; o0.w = acc[i][3] + bv0.w;
            o1.x = acc[i][4] + bv1.x; o1.y = acc[i][5] + bv1.y;
            o1.z = acc[i][6] + bv1.z; o1.w = acc[i][7] + bv1.w;
            *reinterpret_cast<float4*>(&C[(size_t)r * Nc + col0 + rn]) = o0;
            *reinterpret_cast<float4*>(&C[(size_t)r * Nc + col0 + rn + 4]) = o1;
        }
    }
}

// ---------------- small SGEMM for final (N=64): 64x64 tile ----------------
__global__ void sgemm64_kernel(const float* __restrict__ A, const float* __restrict__ B,
                               const float* __restrict__ bias, float* __restrict__ C,
                               int M, int Nc, int K) {
    __shared__ float As[64][32];
    __shared__ float Bs[32][64];
    int tid = threadIdx.x;
    int tx = tid & 15;
    int ty = tid >> 4;
    int row0 = blockIdx.y * 64;
    int col0 = blockIdx.x * 64;

    float acc[4][4];
    #pragma unroll
    for (int i = 0; i < 4; i++)
        #pragma unroll
        for (int j = 0; j < 4; j++) acc[i][j] = 0.0f;

    for (int kk = 0; kk < K; kk += 32) {
        #pragma unroll
        for (int i = 0; i < 2; i++) {
            int f = tid + i * 256;
            int r = f >> 3;
            int c4 = f & 7;
            int grow = row0 + r;
            float4 av = make_float4(0.f, 0.f, 0.f, 0.f);
            if (grow < M)
                av = *reinterpret_cast<const float4*>(&A[(size_t)grow * K + kk + c4 * 4]);
            *reinterpret_cast<float4*>(&As[r][c4 * 4]) = av;
        }
        #pragma unroll
        for (int i = 0; i < 2; i++) {
            int f = tid + i * 256;
            int r = f >> 4;
            int c4 = f & 15;
            float4 bv = *reinterpret_cast<const float4*>(&B[(size_t)(kk + r) * Nc + col0 + c4 * 4]);
            *reinterpret_cast<float4*>(&Bs[r][c4 * 4]) = bv;
        }
        __syncthreads();
        #pragma unroll
        for (int k = 0; k < 32; k++) {
            float4 bv = *reinterpret_cast<const float4*>(&Bs[k][tx * 4]);
            float a0 = As[ty * 4 + 0][k];
            float a1 = As[ty * 4 + 1][k];
            float a2 = As[ty * 4 + 2][k];
            float a3 = As[ty * 4 + 3][k];
            acc[0][0] += a0 * bv.x; acc[0][1] += a0 * bv.y; acc[0][2] += a0 * bv.z; acc[0][3] += a0 * bv.w;
            acc[1][0] += a1 * bv.x; acc[1][1] += a1 * bv.y; acc[1][2] += a1 * bv.z; acc[1][3] += a1 * bv.w;
            acc[2][0] += a2 * bv.x; acc[2][1] += a2 * bv.y; acc[2][2] += a2 * bv.z; acc[2][3] += a2 * bv.w;
            acc[3][0] += a3 * bv.x; acc[3][1] += a3 * bv.y; acc[3][2] += a3 * bv.z; acc[3][3] += a3 * bv.w;
        }
        __syncthreads();
    }

    float4 bv4 = make_float4(0.f, 0.f, 0.f, 0.f);
    if (bias) bv4 = *reinterpret_cast<const float4*>(&bias[col0 + tx * 4]);
    #pragma unroll
    for (int i = 0; i < 4; i++) {
        int r = row0 + ty * 4 + i;
        if (r < M) {
            float4 o;
            o.x = acc[i][0] + bv4.x;
            o.y = acc[i][1] + bv4.y;
            o.z = acc[i][2] + bv4.z;
            o.w = acc[i][3] + bv4.w;
            *reinterpret_cast<float4*>(&C[(size_t)r * Nc + col0 + tx * 4]) = o;
        }
    }
}

// ---------------- launch ----------------
extern "C" void kernel_launch(void* const* d_in, const int* in_sizes, int n_in,
                              void* d_out, int out_size) {
    const float* x_in  = (const float*)d_in[0];
    const float* WL    = (const float*)d_in[1];
    const float* bL    = (const float*)d_in[2];
    const float* WG    = (const float*)d_in[3];
    const float* bG    = (const float*)d_in[4];
    const float* linW  = (const float*)d_in[5];
    const float* linb  = (const float*)d_in[6];
    const float* ln_g  = (const float*)d_in[7];
    const float* ln_b  = (const float*)d_in[8];
    const float* finW  = (const float*)d_in[9];
    const float* finb  = (const float*)d_in[10];
    const int*   Ge    = (const int*)d_in[11];
    const int*   Le    = (const int*)d_in[12];
    int E_G = in_sizes[11] / 2;
    int E_L = in_sizes[12] / 2;
    float* out = (float*)d_out;

    float *px, *phG, *phL, *pxcat, *pdinvG, *pdinvL, *pcoefG, *pcoefL;
    int *pdegG, *pdegL, *prowG, *prowL, *pfillG, *pfillL, *pcolG, *pcolL, *pbsum;
    cudaGetSymbolAddress((void**)&px,     g_x);
    cudaGetSymbolAddress((void**)&phG,    g_hG);
    cudaGetSymbolAddress((void**)&phL,    g_hL);
    cudaGetSymbolAddress((void**)&pxcat,  g_xcat);
    cudaGetSymbolAddress((void**)&pdegG,  g_degG);
    cudaGetSymbolAddress((void**)&pdegL,  g_degL);
    cudaGetSymbolAddress((void**)&pdinvG, g_dinvG);
    cudaGetSymbolAddress((void**)&pdinvL, g_dinvL);
    cudaGetSymbolAddress((void**)&prowG,  g_rowptrG);
    cudaGetSymbolAddress((void**)&prowL,  g_rowptrL);
    cudaGetSymbolAddress((void**)&pfillG, g_fillG);
    cudaGetSymbolAddress((void**)&pfillL, g_fillL);
    cudaGetSymbolAddress((void**)&pcolG,  g_colG);
    cudaGetSymbolAddress((void**)&pcolL,  g_colL);
    cudaGetSymbolAddress((void**)&pcoefG, g_coefG);
    cudaGetSymbolAddress((void**)&pcoefL, g_coefL);
    cudaGetSymbolAddress((void**)&pbsum,  g_bsum);

    cudaMemcpyAsync(px, x_in, (size_t)NN * HH * sizeof(float), cudaMemcpyDeviceToDevice);

    // degrees + dinv
    zero_deg_kernel<<<NB196, 256>>>(pdegG, pdegL, NN);
    count_deg_kernel<<<(E_G + 255) / 256, 256>>>(Ge + E_G, E_G, pdegG);
    count_deg_kernel<<<(E_L + 255) / 256, 256>>>(Le + E_L, E_L, pdegL);
    make_dinv_kernel<<<NB196, 256>>>(pdegG, pdinvG, pdegL, pdinvL, NN);

    // CSR build: G
    scan_block_kernel<<<NB196, 256>>>(pdegG, prowG, pbsum, NN);
    scan_aux_kernel<<<1, 32>>>(pbsum, NB196);
    scan_add_kernel<<<NB196, 256>>>(prowG, pfillG, pbsum, NN, E_G);
    fill_csr_kernel<<<(E_G + 255) / 256, 256>>>(Ge, Ge + E_G, E_G, pfillG, pcolG, pcoefG, pdinvG);
    // CSR build: L
    scan_block_kernel<<<NB196, 256>>>(pdegL, prowL, pbsum, NN);
    scan_aux_kernel<<<1, 32>>>(pbsum, NB196);
    scan_add_kernel<<<NB196, 256>>>(prowL, pfillL, pbsum, NN, E_L);
    fill_csr_kernel<<<(E_L + 255) / 256, 256>>>(Le, Le + E_L, E_L, pfillL, pcolL, pcoefL, pdinvL);

    dim3 gH(1, (NN + 127) / 128);
    int gatherBlocks = (NN * 32 + 255) / 256;   // 8 warps per block, 1 node per warp

    for (int i = 0; i < DEPTH; i++) {
        sgemm128_kernel<<<gH, 256>>>(px, WG + (size_t)i * HH * HH, nullptr, phG, NN, HH, HH);
        sgemm128_kernel<<<gH, 256>>>(px, WL + (size_t)i * HH * HH, nullptr, phL, NN, HH, HH);
        int res = (i > 0) ? 1 : 0;
        gather_ln_kernel<<<gatherBlocks, 256>>>((const float4*)phG, (const float4*)px,
                                                prowG, pcolG, pcoefG, pdinvG,
                                                (const float4*)(bG + (size_t)i * HH),
                                                (const float4*)ln_g, (const float4*)ln_b,
                                                (float4*)pxcat, 0, res);
        gather_ln_kernel<<<gatherBlocks, 256>>>((const float4*)phL, (const float4*)px,
                                                prowL, pcolL, pcoefL, pdinvL,
                                                (const float4*)(bL + (size_t)i * HH),
                                                (const float4*)ln_g, (const float4*)ln_b,
                                                (float4*)pxcat, 1, res);
        sgemm128_kernel<<<gH, 256>>>(pxcat, linW + (size_t)i * 2 * HH * HH,
                                     linb + (size_t)i * HH, px, NN, HH, 2 * HH);
    }

    dim3 gF(1, (NN + 63) / 64);
    sgemm64_kernel<<<gF, 256>>>(px, finW, finb, out, NN, OUTC, HH);
    cudaMemcpyAsync(out + (size_t)NN * OUTC, px, (size_t)NN * HH * sizeof(float),
                    cudaMemcpyDeviceToDevice);
}